// round 3
// baseline (speedup 1.0000x reference)
#include <cuda_runtime.h>
#include <cstdint>
#include <cstddef>

// Problem constants (fixed by the reference)
#define NN 100000
#define EE 600000
#define DD 128
#define LL 5
#define BN_EPS 1e-5f

// ---------------------------------------------------------------------------
// Device scratch (all vector-accessed arrays 16B aligned)
// ---------------------------------------------------------------------------
__device__ __align__(16) float         g_hl[(size_t)NN * DD];  // post-linear features
__device__ __align__(16) float         g_hn[(size_t)NN * DD];  // aggregation buffer
__device__ __align__(16) unsigned char g_ea[(size_t)EE * DD];  // edge_attr packed u8
__device__ __align__(16) int           g_row[EE];
__device__ __align__(16) int           g_col[EE];
__device__ __align__(16) float         g_norm[EE];
__device__ __align__(16) int           g_degcnt[NN];
__device__ __align__(16) float         g_invdeg[NN];
__device__ __align__(16) float         g_dinv[NN];
__device__ __align__(16) float         g_scl[LL * DD];  // gamma*rsqrt(var+eps)
__device__ __align__(16) float         g_sft[LL * DD];  // beta - mean*scale
__device__ int g_is64;                                  // edge_index dtype flag

// ---------------------------------------------------------------------------
// Preprocessing kernels
// ---------------------------------------------------------------------------

// Detect whether edge_index is int64 or int32.
// If int64 (values < 2^17 >= 0), every odd 32-bit word is 0.
// If int32, odd words are random node ids -> OR is nonzero w.p. ~1.
// Reading 8192 int32 words is within bounds under both interpretations
// (buffer holds 2*E elements of >= 4 bytes each).
__global__ void k_detect(const int* __restrict__ ei32) {
    __shared__ int s_any;
    if (threadIdx.x == 0) s_any = 0;
    __syncthreads();
    int v = 0;
    for (int i = threadIdx.x; i < 4096; i += blockDim.x)
        v |= ei32[2 * i + 1];
    atomicOr(&s_any, v);
    __syncthreads();
    if (threadIdx.x == 0) g_is64 = (s_any == 0) ? 1 : 0;
}

__global__ void k_zero_deg() {
    int i = blockIdx.x * blockDim.x + threadIdx.x;
    if (i < NN) g_degcnt[i] = 0;
}

__global__ void k_edge_pre(const void* __restrict__ ei) {
    int e = blockIdx.x * blockDim.x + threadIdx.x;
    if (e >= EE) return;
    int r, c;
    if (g_is64) {
        const long long* p = (const long long*)ei;
        r = (int)p[e];
        c = (int)p[EE + e];
    } else {
        const int* p = (const int*)ei;
        r = p[e];
        c = p[EE + e];
    }
    // clamp defensively: converts any dtype surprise into a visible rel_err,
    // not an illegal access
    r = min(max(r, 0), NN - 1);
    c = min(max(c, 0), NN - 1);
    g_row[e] = r;
    g_col[e] = c;
    atomicAdd(&g_degcnt[r], 1);
}

// Pack int32 edge_attr (values 0..3) -> uint8, 4 at a time
__global__ void k_pack(const int4* __restrict__ ea) {
    int i = blockIdx.x * blockDim.x + threadIdx.x;
    if (i >= EE * DD / 4) return;
    int4 v = ea[i];
    unsigned int u = ((unsigned)v.x & 0xffu)
                   | (((unsigned)v.y & 0xffu) << 8)
                   | (((unsigned)v.z & 0xffu) << 16)
                   | (((unsigned)v.w & 0xffu) << 24);
    ((unsigned int*)g_ea)[i] = u;
}

__global__ void k_node() {
    int n = blockIdx.x * blockDim.x + threadIdx.x;
    if (n >= NN) return;
    float d = (float)(g_degcnt[n] + 1);
    g_invdeg[n] = 1.0f / d;
    g_dinv[n]   = rsqrtf(d);
}

__global__ void k_normk() {
    int e = blockIdx.x * blockDim.x + threadIdx.x;
    if (e >= EE) return;
    g_norm[e] = g_dinv[g_row[e]] * g_dinv[g_col[e]];
}

__global__ void k_bnconst(const float* __restrict__ gamma, const float* __restrict__ beta,
                          const float* __restrict__ mean,  const float* __restrict__ var) {
    int i = blockIdx.x * blockDim.x + threadIdx.x;
    if (i >= LL * DD) return;
    float s = gamma[i] * rsqrtf(var[i] + BN_EPS);
    g_scl[i] = s;
    g_sft[i] = beta[i] - mean[i] * s;
}

// ---------------------------------------------------------------------------
// Fused GEMM: hl = affine_relu(A) @ W^T + b ; hn_init = relu(hl+root)*invdeg
//   A   : x for layer 0, else g_hn of previous layer (pass nullptr)
//   aff : -1 identity, else offset into g_scl/g_sft (fold prev BN+relu)
// 128x128 tile, 256 threads, 8x8 per thread, BK=8.
// In-place safe: each block reads only its own 128 rows of A and writes the
// same rows in the epilogue, after all reads (syncthreads-ordered).
// ---------------------------------------------------------------------------
__global__ __launch_bounds__(256)
void k_gemm(const float* __restrict__ A_in, const float* __restrict__ W,
            const float* __restrict__ bias, const float* __restrict__ root,
            int aff)
{
    __shared__ float As[8][132];
    __shared__ float Bs[8][132];
    __shared__ float s_scl[DD];
    __shared__ float s_sft[DD];

    const float* A = A_in ? A_in : g_hn;

    int tid = threadIdx.x;
    int tx  = tid & 15;        // col group
    int ty  = tid >> 4;        // row group
    int rowbase = blockIdx.x * 128;

    if (aff >= 0 && tid < DD) {
        s_scl[tid] = g_scl[aff + tid];
        s_sft[tid] = g_sft[aff + tid];
    }
    __syncthreads();

    int lm = tid >> 1;          // 0..127 : A row / W row (output feature)
    int lk = (tid & 1) * 4;     // 0 or 4 : k sub-offset

    int arow = rowbase + lm;
    if (arow >= NN) arow = NN - 1;                     // clamp (last block only)
    const float4* Arow4 = (const float4*)(A + (size_t)arow * DD);
    const float4* Wrow4 = (const float4*)(W + (size_t)lm * DD);

    float acc[8][8];
    #pragma unroll
    for (int i = 0; i < 8; i++)
        #pragma unroll
        for (int j = 0; j < 8; j++) acc[i][j] = 0.f;

    for (int kt = 0; kt < 16; ++kt) {
        float4 av = __ldg(&Arow4[kt * 2 + (tid & 1)]);
        if (aff >= 0) {
            int kb = kt * 8 + lk;
            av.x = fmaxf(fmaf(av.x, s_scl[kb + 0], s_sft[kb + 0]), 0.f);
            av.y = fmaxf(fmaf(av.y, s_scl[kb + 1], s_sft[kb + 1]), 0.f);
            av.z = fmaxf(fmaf(av.z, s_scl[kb + 2], s_sft[kb + 2]), 0.f);
            av.w = fmaxf(fmaf(av.w, s_scl[kb + 3], s_sft[kb + 3]), 0.f);
        }
        float4 wv = __ldg(&Wrow4[kt * 2 + (tid & 1)]);

        __syncthreads();
        As[lk + 0][lm] = av.x; As[lk + 1][lm] = av.y;
        As[lk + 2][lm] = av.z; As[lk + 3][lm] = av.w;
        Bs[lk + 0][lm] = wv.x; Bs[lk + 1][lm] = wv.y;
        Bs[lk + 2][lm] = wv.z; Bs[lk + 3][lm] = wv.w;
        __syncthreads();

        #pragma unroll
        for (int kk = 0; kk < 8; ++kk) {
            float a[8], bb[8];
            *(float4*)&a[0]  = *(const float4*)&As[kk][ty * 8];
            *(float4*)&a[4]  = *(const float4*)&As[kk][ty * 8 + 4];
            *(float4*)&bb[0] = *(const float4*)&Bs[kk][tx * 8];
            *(float4*)&bb[4] = *(const float4*)&Bs[kk][tx * 8 + 4];
            #pragma unroll
            for (int i = 0; i < 8; i++)
                #pragma unroll
                for (int j = 0; j < 8; j++)
                    acc[i][j] = fmaf(a[i], bb[j], acc[i][j]);
        }
    }

    // Epilogue: bias, self-loop init
    float bias_r[8], root_r[8];
    *(float4*)&bias_r[0] = __ldg((const float4*)&bias[tx * 8]);
    *(float4*)&bias_r[4] = __ldg((const float4*)&bias[tx * 8 + 4]);
    *(float4*)&root_r[0] = __ldg((const float4*)&root[tx * 8]);
    *(float4*)&root_r[4] = __ldg((const float4*)&root[tx * 8 + 4]);

    #pragma unroll
    for (int i = 0; i < 8; i++) {
        int r = rowbase + ty * 8 + i;
        if (r >= NN) continue;
        float idg = g_invdeg[r];
        float hv[8], sv[8];
        #pragma unroll
        for (int j = 0; j < 8; j++) {
            hv[j] = acc[i][j] + bias_r[j];
            sv[j] = fmaxf(hv[j] + root_r[j], 0.f) * idg;
        }
        float* hlp = g_hl + (size_t)r * DD + tx * 8;
        float* hnp = g_hn + (size_t)r * DD + tx * 8;
        *(float4*)&hlp[0] = *(float4*)&hv[0];
        *(float4*)&hlp[4] = *(float4*)&hv[4];
        *(float4*)&hnp[0] = *(float4*)&sv[0];
        *(float4*)&hnp[4] = *(float4*)&sv[4];
    }
}

// ---------------------------------------------------------------------------
// Edge scatter: one warp per edge, lane handles 4 features.
//   msg = norm[e] * relu(hl[row] + e_attr) ; hn[col] += msg (128b vector red)
// ---------------------------------------------------------------------------
__global__ __launch_bounds__(256)
void k_edge()
{
    int warp = (blockIdx.x * blockDim.x + threadIdx.x) >> 5;
    int lane = threadIdx.x & 31;
    if (warp >= EE) return;
    int e = warp;

    int   r   = g_row[e];
    int   c   = g_col[e];
    float nrm = g_norm[e];

    float4 h4 = __ldg((const float4*)(g_hl + (size_t)r * DD) + lane);
    unsigned int u = __ldcs((const unsigned int*)g_ea + (size_t)e * 32 + lane);

    float4 m;
    m.x = fmaxf(h4.x + (float)( u        & 0xffu), 0.f) * nrm;
    m.y = fmaxf(h4.y + (float)((u >>  8) & 0xffu), 0.f) * nrm;
    m.z = fmaxf(h4.z + (float)((u >> 16) & 0xffu), 0.f) * nrm;
    m.w = fmaxf(h4.w + (float)((u >> 24) & 0xffu), 0.f) * nrm;

    atomicAdd((float4*)(g_hn + (size_t)c * DD) + lane, m);
}

// ---------------------------------------------------------------------------
// Final BN (layer 4, no relu) -> d_out
// ---------------------------------------------------------------------------
__global__ void k_out(float* __restrict__ out)
{
    int i4 = blockIdx.x * blockDim.x + threadIdx.x;     // float4 index
    if (i4 >= NN * DD / 4) return;
    int k = (i4 & 31) * 4;
    const float* scl = g_scl + 4 * DD + k;
    const float* sft = g_sft + 4 * DD + k;
    float4 v = *((const float4*)g_hn + i4);
    v.x = fmaf(v.x, scl[0], sft[0]);
    v.y = fmaf(v.y, scl[1], sft[1]);
    v.z = fmaf(v.z, scl[2], sft[2]);
    v.w = fmaf(v.w, scl[3], sft[3]);
    ((float4*)out)[i4] = v;
}

// ---------------------------------------------------------------------------
// Host driver (graph-capturable: kernel launches only)
// ---------------------------------------------------------------------------
extern "C" void kernel_launch(void* const* d_in, const int* in_sizes, int n_in,
                              void* d_out, int out_size)
{
    const float* x     = (const float*)d_in[0];
    const void*  ei    = d_in[1];                 // int64 or int32, detected on device
    const int*   ea    = (const int*)d_in[2];
    const float* W     = (const float*)d_in[3];
    const float* b     = (const float*)d_in[4];
    const float* root  = (const float*)d_in[5];
    const float* gamma = (const float*)d_in[6];
    const float* beta  = (const float*)d_in[7];
    const float* mean  = (const float*)d_in[8];
    const float* var   = (const float*)d_in[9];
    (void)in_sizes; (void)n_in; (void)out_size;

    // Preprocessing (once per launch, deterministic)
    k_detect<<<1, 256>>>((const int*)ei);
    k_zero_deg<<<(NN + 255) / 256, 256>>>();
    k_edge_pre<<<(EE + 255) / 256, 256>>>(ei);
    k_pack<<<(EE * DD / 4 + 255) / 256, 256>>>((const int4*)ea);
    k_bnconst<<<(LL * DD + 255) / 256, 256>>>(gamma, beta, mean, var);
    k_node<<<(NN + 255) / 256, 256>>>();
    k_normk<<<(EE + 255) / 256, 256>>>();

    const int gemm_blocks = (NN + 127) / 128;   // 782
    const int edge_blocks = (EE + 7) / 8;       // 75000 (8 warps/block)

    for (int l = 0; l < LL; ++l) {
        const float* A   = (l == 0) ? x : nullptr;       // nullptr -> g_hn inside
        int          aff = (l == 0) ? -1 : (l - 1) * DD; // fold BN(l-1)+relu into A load
        k_gemm<<<gemm_blocks, 256>>>(A, W + (size_t)l * DD * DD,
                                     b + (size_t)l * DD, root + (size_t)l * DD, aff);
        k_edge<<<edge_blocks, 256>>>();
    }
    k_out<<<(NN * DD / 4 + 255) / 256, 256>>>((float*)d_out);
}